// round 17
// baseline (speedup 1.0000x reference)
#include <cuda_runtime.h>
#include <cuda_fp16.h>
#include <cstdint>

// PointConv2d fused (round 10): R14 layout with corrected A row stride.
// ASTRIDE=208 (13 chunks) so the 4-class XOR swizzle ({0..3}<<4) never
// escapes the row (chunks q<=9, q^3<=11<13). fp16 mma, smem B double-
// buffered, cp.async pipeline, row-major A [p][slot], slot=ci*10+o.
// B=8, N=16384, K=9, C=64 -> CIN=66, O=9, CO=64, FAN=594.

namespace {
constexpr int B_   = 8;
constexpr int N_   = 16384;
constexpr int K_   = 9;
constexpr int CF_  = 64;
constexpr int CIN_ = 66;
constexpr int O_   = 9;
constexpr int CO_  = 64;
constexpr int FAN_ = 594;

constexpr int TM      = 128;
constexpr int THREADS = 256;
constexpr int CPC     = 8;    // channels per chunk
constexpr int NCH     = 9;    // chunks
constexpr int KSTEPS  = 5;    // 80 slots / 16

constexpr int BSTRIDE = 176;  // B smem row stride bytes (160 data + pad)
constexpr int ASTRIDE = 208;  // A smem row stride bytes (13 chunks; swizzle-safe)

// shared memory byte offsets
constexpr int SM_PRM  = 0;                          // 181 floats -> 768
constexpr int SM_A    = 768;                        // 128*208 = 26624 (end 27392)
constexpr int SM_B0   = 42240;                      // ws alias = [768, 42240)
constexpr int SM_B1   = SM_B0 + CO_ * BSTRIDE;      // 53504
constexpr int SM_FEAT = SM_B1 + CO_ * BSTRIDE;      // 64768
constexpr int SM_TOT  = SM_FEAT + CPC * TM * K_ * 4;  // 101632
// ws alias: [768, 42240) covers A region (dead before A written)
// epilogue tb alias at SM_A: 64*132*4 = 33792 -> [768, 34560) < 42240 ok
}

// prepacked reordered fp16 linear weights: [chunk][co][88]; slot = ci*10+o
__device__ __half g_Bh[NCH * CO_ * 88];

// ---------------- helpers ----------------
__device__ __forceinline__ uint32_t smem_u32(const void* p) {
    uint32_t a;
    asm("{ .reg .u64 t; cvta.to.shared.u64 t, %1; cvt.u32.u64 %0, t; }"
        : "=r"(a) : "l"(p));
    return a;
}
__device__ __forceinline__ uint64_t pack2(float lo, float hi) {
    uint64_t r;
    asm("mov.b64 %0, {%1, %2};" : "=l"(r) : "f"(lo), "f"(hi));
    return r;
}
__device__ __forceinline__ void unpack2(uint64_t v, float& a, float& b) {
    asm("mov.b64 {%0, %1}, %2;" : "=f"(a), "=f"(b) : "l"(v));
}
__device__ __forceinline__ uint64_t fma2(uint64_t a, uint64_t b, uint64_t c) {
    uint64_t r;
    asm("fma.rn.f32x2 %0, %1, %2, %3;" : "=l"(r) : "l"(a), "l"(b), "l"(c));
    return r;
}
__device__ __forceinline__ void ldsm_x4(uint32_t* r, uint32_t a) {
    asm volatile("ldmatrix.sync.aligned.m8n8.x4.shared.b16 {%0,%1,%2,%3}, [%4];"
        : "=r"(r[0]), "=r"(r[1]), "=r"(r[2]), "=r"(r[3]) : "r"(a));
}
__device__ __forceinline__ void mma16816(float* d, const uint32_t* a,
                                         uint32_t b0, uint32_t b1) {
    asm volatile("mma.sync.aligned.m16n8k16.row.col.f32.f16.f16.f32 "
        "{%0,%1,%2,%3}, {%4,%5,%6,%7}, {%8,%9}, {%0,%1,%2,%3};"
        : "+f"(d[0]), "+f"(d[1]), "+f"(d[2]), "+f"(d[3])
        : "r"(a[0]), "r"(a[1]), "r"(a[2]), "r"(a[3]), "r"(b0), "r"(b1));
}
__device__ __forceinline__ void cp16(uint32_t dst, const void* src, uint32_t bytes) {
    asm volatile("cp.async.cg.shared.global [%0], [%1], 16, %2;"
        :: "r"(dst), "l"(src), "r"(bytes) : "memory");
}
#define CP_COMMIT() asm volatile("cp.async.commit_group;" ::: "memory")
#define CP_WAIT(n)  asm volatile("cp.async.wait_group %0;" :: "n"(n) : "memory")
__device__ __forceinline__ float leaky(float x) { return fmaxf(x, 0.1f * x); }
__device__ __forceinline__ void sts_h2(void* addr, float a, float b) {
    const __half2 h = __floats2half2_rn(a, b);
    *(__half2*)addr = h;
}

// ---------------- prep: reorder lin_w, fp16, slot = ci*10 + o ----------------
__global__ void pc_prep(const float* __restrict__ lw) {
    int idx = blockIdx.x * blockDim.x + threadIdx.x;
    if (idx >= NCH * CO_ * 88) return;
    const int kk = idx % 88;
    const int co = (idx / 88) % CO_;
    const int ck = idx / (88 * CO_);
    float v = 0.0f;
    if (kk < 80) {
        const int c = ck * CPC + kk / 10;
        const int o = kk % 10;
        if (o < O_ && c < CIN_) v = lw[co * FAN_ + o * CIN_ + c];
    }
    g_Bh[idx] = __float2half_rn(v);
}

// ---------------- main kernel ----------------
__global__ __launch_bounds__(THREADS, 2)
void pc_main(const float* __restrict__ xy,    // [B,2,N,K]
             const float* __restrict__ knnf,  // [B,64,N,K]
             const float* __restrict__ w1, const float* __restrict__ b1,
             const float* __restrict__ w2, const float* __restrict__ b2,
             const float* __restrict__ lb,    // [64]
             float* __restrict__ out)         // [B,64,N]
{
    extern __shared__ char smc[];
    const uint32_t sb = smem_u32(smc);
    float* prm   = (float*)(smc + SM_PRM);
    float* ws    = (float*)(smc + SM_A);     // alias [768,42240), dead before A written
    float* featf = (float*)(smc + SM_FEAT);

    const int t    = threadIdx.x;
    const int lane = t & 31;
    const int wid  = t >> 5;
    const int b    = blockIdx.y;
    const int n0   = blockIdx.x * TM;

    // ---- async staging helpers (div-free) ----
    auto stage_feat_async = [&](int ck) {
        if (ck >= NCH) return;
        const int ci = t >> 5;                 // channel within chunk
        const int c  = ck * CPC + ci;
        const char* src;
        uint32_t bytes = 16;
        if (c < 2)
            src = (const char*)(xy + ((size_t)(2 * b + c) * N_ + n0) * K_);
        else if (c < CIN_)
            src = (const char*)(knnf + ((size_t)(CF_ * b + (c - 2)) * N_ + n0) * K_);
        else { src = (const char*)xy; bytes = 0; }   // zero-fill
        const uint32_t dbase = sb + SM_FEAT + (uint32_t)(ci * 288) * 16;
        const int r0 = t & 31;
#pragma unroll
        for (int q = 0; q < 9; q++) {
            const int rem = r0 + q * 32;
            cp16(dbase + (uint32_t)rem * 16, src + (size_t)rem * 16, bytes);
        }
    };
    auto stage_B_async = [&](int ck) {
        if (ck >= NCH) return;
        const uint32_t dst = sb + ((ck & 1) ? SM_B1 : SM_B0);
        const char* gh = (const char*)(g_Bh + ck * (CO_ * 88));
        for (int i = t; i < 704; i += THREADS)
            cp16(dst + (uint32_t)i * 16, gh + i * 16, 16);
    };

    // prologue: prefetch feat(0), B(0)
    stage_feat_async(0);
    CP_COMMIT();                  // group F0
    stage_B_async(0);
    CP_COMMIT();                  // group B0

    // stage params
    if (t < 18)        prm[t] = w1[t];
    else if (t < 27)   prm[t] = b1[t - 18];
    else if (t < 108)  prm[t] = w2[t - 27];
    else if (t < 117)  prm[t] = b2[t - 108];
    else if (t < 181)  prm[t] = lb[t - 117];

    CP_WAIT(1);                   // F0 done (B0 pending)
    __syncthreads();

    // ---- WeightNet: ws[p][o*9+k] from staged xy (feat c0, c1) ----
    for (int task = t; task < TM * K_; task += THREADS) {
        const int p2 = task & 127;
        const int k  = task >> 7;
        const float x0 = featf[p2 * K_ + k];
        const float x1 = featf[TM * K_ + p2 * K_ + k];
        float h[O_];
#pragma unroll
        for (int j = 0; j < O_; j++)
            h[j] = leaky(fmaf(prm[2 * j], x0, fmaf(prm[2 * j + 1], x1, prm[18 + j])));
#pragma unroll
        for (int o = 0; o < O_; o++) {
            float v = prm[108 + o];
#pragma unroll
            for (int j = 0; j < O_; j++) v = fmaf(prm[27 + o * O_ + j], h[j], v);
            ws[p2 * 81 + o * 9 + k] = leaky(v);
        }
    }
    __syncthreads();

    // ---- per-thread w pairs (f32x2 over o) ----
    const int p  = t & 127;
    const int hh = t >> 7;
    uint64_t wpA[9], wpB[9];
    float w8[9];
    {
        const float* wr = ws + p * 81;
        const int ob = hh * 36;
#pragma unroll
        for (int k = 0; k < 9; k++) {
            wpA[k] = pack2(wr[ob + k],      wr[ob + 9 + k]);
            wpB[k] = pack2(wr[ob + 18 + k], wr[ob + 27 + k]);
            w8[k]  = wr[72 + k];
        }
    }
    __syncthreads();   // ws dead; A region writable

    float acc[2][4][4];
#pragma unroll
    for (int mi = 0; mi < 2; mi++)
#pragma unroll
        for (int j = 0; j < 4; j++)
#pragma unroll
            for (int q = 0; q < 4; q++) acc[mi][j][q] = 0.0f;

    const uint32_t aA = sb + SM_A;

    // A production row base + thread-constant swizzle
    char* arow = smc + SM_A + p * ASTRIDE;
    const uint32_t swz = (uint32_t)((p >> 3) & 3) << 4;

    // warp tile: 32 points x 32 co
    const int mrow = (wid & 3) * 32;
    const int nc0j = (wid >> 2) * 4;

#pragma unroll 1
    for (int ck = 0; ck < NCH; ck++) {
        // ---- produce A chunk from staged features ----
#pragma unroll
        for (int ci = 0; ci < CPC; ci++) {
            const float* fp = featf + ci * (TM * K_) + p * K_;
            float f[9];
#pragma unroll
            for (int k = 0; k < 9; k++) f[k] = fp[k];
            uint64_t a0 = pack2(0.f, 0.f), a1 = pack2(0.f, 0.f);
            float s8 = 0.f;
#pragma unroll
            for (int k = 0; k < 9; k++) {
                const uint64_t ff = pack2(f[k], f[k]);
                a0 = fma2(ff, wpA[k], a0);
                a1 = fma2(ff, wpB[k], a1);
                if (hh) s8 = fmaf(f[k], w8[k], s8);
            }
            float v0, v1, v2, v3;
            unpack2(a0, v0, v1);
            unpack2(a1, v2, v3);
            const uint32_t base = 20 * ci;   // slot byte offset = (ci*10 + o)*2
            if (hh == 0) {
                sts_h2(arow + ((base +  0) ^ swz), v0, v1);   // o0,o1
                sts_h2(arow + ((base +  4) ^ swz), v2, v3);   // o2,o3
            } else {
                sts_h2(arow + ((base +  8) ^ swz), v0, v1);   // o4,o5
                sts_h2(arow + ((base + 12) ^ swz), v2, v3);   // o6,o7
                sts_h2(arow + ((base + 16) ^ swz), s8, 0.f);  // o8, pad
            }
        }

        CP_WAIT(0);         // B(ck) landed
        __syncthreads();    // A(ck) + B(ck) visible to all

        // prefetch feat(ck+1) and B(ck+1) during mma
        stage_feat_async(ck + 1);
        CP_COMMIT();        // group F(ck+1)
        stage_B_async(ck + 1);
        CP_COMMIT();        // group B(ck+1)

        // ---- mma: warp tile 32p x 32co ----
        {
            const uint32_t aBh = sb + ((ck & 1) ? SM_B1 : SM_B0);
            const int Lr = lane & 15;        // A row within 16
            const int Lc = lane >> 4;        // A k-halfblock
            const int r  = lane & 7;
            const int tq = lane >> 3;
#pragma unroll
            for (int s = 0; s < KSTEPS; s++) {
                uint32_t ah[2][4];
#pragma unroll
                for (int mi = 0; mi < 2; mi++) {
                    const int m = mrow + mi * 16 + Lr;
                    const uint32_t byte =
                        (uint32_t)(s * 32 + Lc * 16) ^ ((uint32_t)((m >> 3) & 3) << 4);
                    ldsm_x4(ah[mi], aA + (uint32_t)(m * ASTRIDE) + byte);
                }
#pragma unroll
                for (int jp = 0; jp < 2; jp++) {
                    const int j = nc0j + 2 * jp;
                    const uint32_t boff =
                        (uint32_t)((8 * (j + (tq >> 1)) + r) * BSTRIDE +
                                   s * 32 + ((tq & 1) << 4));
                    uint32_t bh[4];
                    ldsm_x4(bh, aBh + boff);
#pragma unroll
                    for (int mi = 0; mi < 2; mi++) {
                        mma16816(acc[mi][2 * jp],     ah[mi], bh[0], bh[1]);
                        mma16816(acc[mi][2 * jp + 1], ah[mi], bh[2], bh[3]);
                    }
                }
            }
        }
        CP_WAIT(1);         // F(ck+1) done (B(ck+1) may be pending)
        __syncthreads();    // A free; feat(ck+1) visible
    }

    // ---- epilogue: transpose through smem, coalesced float4 stores ----
    {
        float* tb = (float*)(smc + SM_A);   // [co][132] f32, conflict-free
        const int rr   = lane >> 2;
        const int col2 = (lane & 3) * 2;
#pragma unroll
        for (int mi = 0; mi < 2; mi++)
#pragma unroll
            for (int jp = 0; jp < 4; jp++) {
                const int co = (nc0j + jp) * 8 + col2;
                const int pr = mrow + mi * 16 + rr;
                tb[co * 132 + pr]           = acc[mi][jp][0];
                tb[(co + 1) * 132 + pr]     = acc[mi][jp][1];
                tb[co * 132 + pr + 8]       = acc[mi][jp][2];
                tb[(co + 1) * 132 + pr + 8] = acc[mi][jp][3];
            }
        __syncthreads();
#pragma unroll
        for (int j = 0; j < 8; j++) {
            const int i  = t + j * 256;
            const int co = i >> 5;
            const int u4 = i & 31;
            float4 v = *(float4*)(tb + co * 132 + u4 * 4);
            const float bi = prm[117 + co];
            v.x = leaky(v.x + bi);
            v.y = leaky(v.y + bi);
            v.z = leaky(v.z + bi);
            v.w = leaky(v.w + bi);
            *(float4*)(out + (size_t)(b * CO_ + co) * N_ + n0 + u4 * 4) = v;
        }
    }
}

extern "C" void kernel_launch(void* const* d_in, const int* in_sizes, int n_in,
                              void* d_out, int out_size)
{
    const float* xy   = (const float*)d_in[0];
    const float* knnf = (const float*)d_in[1];
    const float* w1   = (const float*)d_in[2];
    const float* b1   = (const float*)d_in[3];
    const float* w2   = (const float*)d_in[4];
    const float* b2   = (const float*)d_in[5];
    const float* lw   = (const float*)d_in[6];
    const float* lb   = (const float*)d_in[7];
    float* out = (float*)d_out;

    pc_prep<<<(NCH * CO_ * 88 + 255) / 256, 256>>>(lw);

    cudaFuncSetAttribute(pc_main, cudaFuncAttributeMaxDynamicSharedMemorySize, SM_TOT);
    dim3 grid(N_ / TM, B_);
    pc_main<<<grid, THREADS, SM_TOT>>>(xy, knnf, w1, b1, w2, b2, lb, out);
}